// round 10
// baseline (speedup 1.0000x reference)
#include <cuda_runtime.h>
#include <cuda_bf16.h>
#include <cstdint>
#include <math.h>

#define N_NODES 50000
#define MPAD    50048   // multiple of 128; pad rows stay zero (.bss)
#define N_EDGES 800000
#define N_GRAPHS 128
#define IN_DIM  100
#define HID     256
#define STEPS   5

// ---------------- scratch (device globals; zero-initialized, no allocation) ----
__device__ float d_h0[MPAD * HID];
__device__ float d_h1[MPAD * HID];
__device__ float d_hs[MPAD * HID];          // scatter accumulator (sum h[src])
__device__ float d_t1[(size_t)N_NODES * (HID / 2)];
__device__ float d_pool[N_GRAPHS * 2 * HID];

__device__ __nv_bfloat16 d_hh0[MPAD * HID], d_hl0[MPAD * HID];
__device__ __nv_bfloat16 d_hh1[MPAD * HID], d_hl1[MPAD * HID];
__device__ __nv_bfloat16 d_ag_hi[MPAD * HID], d_ag_lo[MPAD * HID];

__device__ __nv_bfloat16 d_wih_hi[768 * 256], d_wih_lo[768 * 256];
__device__ __nv_bfloat16 d_whh_hi[768 * 256], d_whh_lo[768 * 256];
__device__ __nv_bfloat16 d_wt_hi [STEPS * 256 * 256], d_wt_lo [STEPS * 256 * 256];
__device__ __nv_bfloat16 d_wa1_hi[128 * 256], d_wa1_lo[128 * 256];
__device__ __nv_bfloat16 d_win_hi[256 * 128], d_win_lo[256 * 128];

// ================= PTX helpers (sm_80-baseline only) =================
__device__ __forceinline__ uint32_t smem_u32(const void* p) {
    uint32_t a;
    asm("{ .reg .u64 t; cvta.to.shared.u64 t, %1; cvt.u32.u64 %0, t; }" : "=r"(a) : "l"(p));
    return a;
}
__device__ __forceinline__ void cp16(uint32_t s, const void* g) {
    asm volatile("cp.async.cg.shared.global [%0], [%1], 16;" :: "r"(s), "l"(g));
}
#define CP_COMMIT() asm volatile("cp.async.commit_group;" ::: "memory")
#define CP_WAIT(N)  asm volatile("cp.async.wait_group %0;" :: "n"(N) : "memory")

__device__ __forceinline__ void ldm4(uint32_t& r0, uint32_t& r1, uint32_t& r2, uint32_t& r3,
                                     uint32_t a) {
    asm volatile("ldmatrix.sync.aligned.m8n8.x4.shared.b16 {%0,%1,%2,%3}, [%4];"
                 : "=r"(r0), "=r"(r1), "=r"(r2), "=r"(r3) : "r"(a));
}
__device__ __forceinline__ void mma_bf16(float* c, const uint32_t* a, const uint32_t* b) {
    asm volatile(
        "mma.sync.aligned.m16n8k16.row.col.f32.bf16.bf16.f32 "
        "{%0,%1,%2,%3}, {%4,%5,%6,%7}, {%8,%9}, {%0,%1,%2,%3};"
        : "+f"(c[0]), "+f"(c[1]), "+f"(c[2]), "+f"(c[3])
        : "r"(a[0]), "r"(a[1]), "r"(a[2]), "r"(a[3]), "r"(b[0]), "r"(b[1]));
}
__device__ __forceinline__ uint32_t pack_bf2(float a, float b) {
    __nv_bfloat16 x = __float2bfloat16(a), y = __float2bfloat16(b);
    return ((uint32_t)__bfloat16_as_ushort(y) << 16) | (uint32_t)__bfloat16_as_ushort(x);
}
__device__ __forceinline__ void split4(float4 v, uint2& uh, uint2& ul) {
    __nv_bfloat16 h0 = __float2bfloat16(v.x), h1 = __float2bfloat16(v.y);
    __nv_bfloat16 h2 = __float2bfloat16(v.z), h3 = __float2bfloat16(v.w);
    uh.x = ((uint32_t)__bfloat16_as_ushort(h1) << 16) | __bfloat16_as_ushort(h0);
    uh.y = ((uint32_t)__bfloat16_as_ushort(h3) << 16) | __bfloat16_as_ushort(h2);
    ul.x = pack_bf2(v.x - __bfloat162float(h0), v.y - __bfloat162float(h1));
    ul.y = pack_bf2(v.z - __bfloat162float(h2), v.w - __bfloat162float(h3));
}

// ================= mma.sync GEMM: C[M, Ntot] = A[M, K] @ B[Ntot, K]^T ==========
// !AF32: A as bf16 hi/lo [MPAD, K]. AF32: A fp32 [Arows, KREAL], split in-kernel.
// Split product: AhBh + AhBl + AlBh, fp32 accumulation.
// CTA 128x128, 8 warps (4x2), warp tile 32x64. K chunk 32, double-buffered.
template <int KTOT, int KREAL, bool AF32, bool WF32, bool WBF16, bool RELU>
__global__ __launch_bounds__(256) void mma_gemm(
    const void* __restrict__ A1, const void* __restrict__ A2,
    const __nv_bfloat16* __restrict__ Bh, const __nv_bfloat16* __restrict__ Bl,
    const float* __restrict__ bias,
    float* __restrict__ Cf, __nv_bfloat16* __restrict__ Cbh, __nv_bfloat16* __restrict__ Cbl,
    int M, int Arows, int Ntot)
{
    constexpr int CH = KTOT / 32;
    constexpr int RSTRIDE = 80;
    constexpr int MAT = 128 * RSTRIDE;   // 10240 B
    extern __shared__ char smem[];
    const uint32_t sb = smem_u32(smem);

    const int tid = threadIdx.x;
    const int wid = tid >> 5, lane = tid & 31;
    const int warp_m = wid & 3, warp_n = wid >> 2;
    const int row0 = blockIdx.y * 128;
    const int ncol0 = blockIdx.x * 128;

    float acc[2][8][4];
#pragma unroll
    for (int tm = 0; tm < 2; tm++)
#pragma unroll
        for (int nt = 0; nt < 8; nt++)
#pragma unroll
            for (int c = 0; c < 4; c++) acc[tm][nt][c] = 0.f;

    auto load_stage = [&](int c, int st) {
        const int k0 = c * 32;
        const uint32_t base = sb + st * (4 * MAT);
        if constexpr (!AF32) {
            const __nv_bfloat16* Ah = (const __nv_bfloat16*)A1;
            const __nv_bfloat16* Al = (const __nv_bfloat16*)A2;
#pragma unroll
            for (int i = 0; i < 2; i++) {
                int l = tid + i * 256;
                int row = l >> 2, q = l & 3;
                uint32_t so = (uint32_t)(row * RSTRIDE + q * 16);
                size_t ea = (size_t)(row0 + row) * KTOT + k0 + q * 8;
                cp16(base + so,       Ah + ea);
                cp16(base + MAT + so, Al + ea);
            }
        }
#pragma unroll
        for (int i = 0; i < 2; i++) {
            int l = tid + i * 256;
            int row = l >> 2, q = l & 3;
            uint32_t so = (uint32_t)(row * RSTRIDE + q * 16);
            size_t eb = (size_t)(ncol0 + row) * KTOT + k0 + q * 8;
            cp16(base + 2 * MAT + so, Bh + eb);
            cp16(base + 3 * MAT + so, Bl + eb);
        }
    };

    load_stage(0, 0);
    CP_COMMIT();

    const int ar = (lane & 7) + ((lane >> 3) & 1) * 8;
    const int akh = lane >> 4;
    const int bn = (lane >> 4);
    const int bk = (lane >> 3) & 1;

    for (int c = 0; c < CH; c++) {
        const int st = c & 1;
        if (c + 1 < CH) {
            load_stage(c + 1, st ^ 1);
            CP_COMMIT();
            CP_WAIT(1);
        } else {
            CP_WAIT(0);
        }
        if constexpr (AF32) {
            // direct fp32 A load + split + sts into stage st (safe: last reads of
            // this stage finished 2 barriers ago)
            const float* Af = (const float*)A1;
            const int k0 = c * 32;
            char* abase = smem + st * (4 * MAT);
#pragma unroll
            for (int i = 0; i < 4; i++) {
                int l = tid + i * 256;           // 1024 float4 per chunk
                int row = l >> 3, q = l & 7;
                float4 v = make_float4(0.f, 0.f, 0.f, 0.f);
                int rg = row0 + row, k = k0 + q * 4;
                if (rg < Arows && k < KREAL)
                    v = *(const float4*)(Af + (size_t)rg * KREAL + k);
                uint2 uh, ul;
                split4(v, uh, ul);
                uint32_t so = (uint32_t)(row * RSTRIDE + q * 8);
                *(uint2*)(abase + so) = uh;
                *(uint2*)(abase + MAT + so) = ul;
            }
        }
        __syncthreads();

        const uint32_t base = sb + st * (4 * MAT);
#pragma unroll
        for (int j = 0; j < 2; j++) {
            uint32_t ah[2][4], al[2][4];
#pragma unroll
            for (int tm = 0; tm < 2; tm++) {
                uint32_t ao = base + (uint32_t)((warp_m * 32 + tm * 16 + ar) * RSTRIDE +
                                                j * 32 + akh * 16);
                ldm4(ah[tm][0], ah[tm][1], ah[tm][2], ah[tm][3], ao);
                ldm4(al[tm][0], al[tm][1], al[tm][2], al[tm][3], ao + MAT);
            }
            uint32_t bh[4][4], bl[4][4];
#pragma unroll
            for (int q = 0; q < 4; q++) {
                int nrow = warp_n * 64 + (2 * q + bn) * 8 + (lane & 7);
                uint32_t bo = base + 2 * MAT +
                              (uint32_t)(nrow * RSTRIDE + j * 32 + bk * 16);
                ldm4(bh[q][0], bh[q][1], bh[q][2], bh[q][3], bo);
                ldm4(bl[q][0], bl[q][1], bl[q][2], bl[q][3], bo + MAT);
            }
#pragma unroll
            for (int tm = 0; tm < 2; tm++)
#pragma unroll
                for (int nt = 0; nt < 8; nt++) {
                    int q = nt >> 1, o = (nt & 1) * 2;
                    mma_bf16(acc[tm][nt], ah[tm], &bh[q][o]);
                    mma_bf16(acc[tm][nt], ah[tm], &bl[q][o]);
                    mma_bf16(acc[tm][nt], al[tm], &bh[q][o]);
                }
        }
        __syncthreads();
    }

    // ---- epilogue ----
#pragma unroll
    for (int tm = 0; tm < 2; tm++) {
        int rbase = row0 + warp_m * 32 + tm * 16 + (lane >> 2);
#pragma unroll
        for (int half = 0; half < 2; half++) {
            int row_g = rbase + half * 8;
            if (row_g >= M) continue;
#pragma unroll
            for (int nt = 0; nt < 8; nt++) {
                int col = ncol0 + warp_n * 64 + nt * 8 + (lane & 3) * 2;
                float v0 = acc[tm][nt][half * 2 + 0];
                float v1 = acc[tm][nt][half * 2 + 1];
                if (bias) { v0 += bias[col]; v1 += bias[col + 1]; }
                if (RELU) { v0 = fmaxf(v0, 0.f); v1 = fmaxf(v1, 0.f); }
                if (WF32)
                    *(float2*)(Cf + (size_t)row_g * Ntot + col) = make_float2(v0, v1);
                if (WBF16) {
                    __nv_bfloat16 h0 = __float2bfloat16(v0);
                    __nv_bfloat16 h1 = __float2bfloat16(v1);
                    float l0 = v0 - __bfloat162float(h0);
                    float l1 = v1 - __bfloat162float(h1);
                    *(uint32_t*)(Cbh + (size_t)row_g * Ntot + col) =
                        ((uint32_t)__bfloat16_as_ushort(h1) << 16) | __bfloat16_as_ushort(h0);
                    *(uint32_t*)(Cbl + (size_t)row_g * Ntot + col) = pack_bf2(l0, l1);
                }
            }
        }
    }
}

// ================= fused gate GEMMs + GRU ====================================
// CTA: 128 nodes x 64 gate-dims; 8 warps (warp_m 0..3, warp_d 0..1), warp 32x32.
// 4 acc groups: r_sum, z_sum, i_n, h_n. K chunks 0-7: A=agg/W_ih; 8-15: A=h/W_hh.
// Epilogue computes the GRU and writes new h (fp32 + bf16 hi/lo) — no gi/gh.
__global__ __launch_bounds__(256, 1) void gate_gru_kernel(
    const __nv_bfloat16* __restrict__ ag_hi, const __nv_bfloat16* __restrict__ ag_lo,
    const __nv_bfloat16* __restrict__ hh_in, const __nv_bfloat16* __restrict__ hl_in,
    const __nv_bfloat16* __restrict__ wih_hi, const __nv_bfloat16* __restrict__ wih_lo,
    const __nv_bfloat16* __restrict__ whh_hi, const __nv_bfloat16* __restrict__ whh_lo,
    const float* __restrict__ b_ih, const float* __restrict__ b_hh,
    const float* __restrict__ h_in,
    float* __restrict__ h_out, __nv_bfloat16* __restrict__ hh_out,
    __nv_bfloat16* __restrict__ hl_out)
{
    constexpr int RS = 80;
    constexpr int STAGE = 51200;   // A hi/lo (2*10240) + 3 groups B hi/lo (3*10240)
    extern __shared__ char smem[];
    const uint32_t sb = smem_u32(smem);
    const int tid = threadIdx.x, wid = tid >> 5, lane = tid & 31;
    const int warp_m = wid & 3, warp_d = wid >> 2;
    const int row0 = blockIdx.y * 128;
    const int d0 = blockIdx.x * 64;

    float acc_r[2][4][4], acc_z[2][4][4], acc_n[2][4][4], acc_hn[2][4][4];
#pragma unroll
    for (int tm = 0; tm < 2; tm++)
#pragma unroll
        for (int nt = 0; nt < 4; nt++)
#pragma unroll
            for (int c = 0; c < 4; c++) {
                acc_r[tm][nt][c] = 0.f; acc_z[tm][nt][c] = 0.f;
                acc_n[tm][nt][c] = 0.f; acc_hn[tm][nt][c] = 0.f;
            }

    auto load_stage = [&](int c, int st) {
        const int phase = c >> 3;
        const int kk = (c & 7) * 32;
        const uint32_t base = sb + st * STAGE;
        const __nv_bfloat16* Ah = phase ? hh_in : ag_hi;
        const __nv_bfloat16* Al = phase ? hl_in : ag_lo;
        const __nv_bfloat16* Wh = phase ? whh_hi : wih_hi;
        const __nv_bfloat16* Wl = phase ? whh_lo : wih_lo;
#pragma unroll
        for (int i = 0; i < 2; i++) {           // A: 512 uint4 each mat
            int l = tid + i * 256;
            int row = l >> 2, q = l & 3;
            uint32_t so = (uint32_t)(row * RS + q * 16);
            size_t ea = (size_t)(row0 + row) * 256 + kk + q * 8;
            cp16(base + so,         Ah + ea);
            cp16(base + 10240 + so, Al + ea);
        }
        {                                        // B: 3 groups x 64 rows
            int row = tid >> 2, q = tid & 3;
#pragma unroll
            for (int g = 0; g < 3; g++) {
                size_t eb = (size_t)(g * 256 + d0 + row) * 256 + kk + q * 8;
                uint32_t bo = base + 20480u + (uint32_t)(g * 10240 + row * RS + q * 16);
                cp16(bo,        Wh + eb);
                cp16(bo + 5120, Wl + eb);
            }
        }
    };

    load_stage(0, 0);
    CP_COMMIT();

    const int ar = (lane & 7) + ((lane >> 3) & 1) * 8;
    const int akh = lane >> 4;
    const int bn = (lane >> 4);
    const int bk = (lane >> 3) & 1;

    auto compute = [&](uint32_t base, float (&a2)[2][4][4]) {
#pragma unroll
        for (int j = 0; j < 2; j++) {
            uint32_t ah[2][4], al[2][4];
#pragma unroll
            for (int tm = 0; tm < 2; tm++) {
                uint32_t ao = base + (uint32_t)((warp_m * 32 + tm * 16 + ar) * RS +
                                                j * 32 + akh * 16);
                ldm4(ah[tm][0], ah[tm][1], ah[tm][2], ah[tm][3], ao);
                ldm4(al[tm][0], al[tm][1], al[tm][2], al[tm][3], ao + 10240);
            }
#pragma unroll
            for (int g = 0; g < 3; g++) {
                uint32_t bh[2][4], bl[2][4];
#pragma unroll
                for (int q = 0; q < 2; q++) {
                    int nrow = warp_d * 32 + (2 * q + bn) * 8 + (lane & 7);
                    uint32_t bo = base + 20480u +
                                  (uint32_t)(g * 10240 + nrow * RS + j * 32 + bk * 16);
                    ldm4(bh[q][0], bh[q][1], bh[q][2], bh[q][3], bo);
                    ldm4(bl[q][0], bl[q][1], bl[q][2], bl[q][3], bo + 5120);
                }
#pragma unroll
                for (int tm = 0; tm < 2; tm++)
#pragma unroll
                    for (int nt = 0; nt < 4; nt++) {
                        int q = nt >> 1, o = (nt & 1) * 2;
                        float* A_ = (g == 0) ? acc_r[tm][nt]
                                  : (g == 1) ? acc_z[tm][nt] : a2[tm][nt];
                        mma_bf16(A_, ah[tm], &bh[q][o]);
                        mma_bf16(A_, ah[tm], &bl[q][o]);
                        mma_bf16(A_, al[tm], &bh[q][o]);
                    }
            }
        }
    };

    for (int c = 0; c < 16; c++) {
        const int st = c & 1;
        if (c + 1 < 16) {
            load_stage(c + 1, st ^ 1);
            CP_COMMIT();
            CP_WAIT(1);
        } else {
            CP_WAIT(0);
        }
        __syncthreads();
        const uint32_t base = sb + st * STAGE;
        if (c < 8) compute(base, acc_n);
        else       compute(base, acc_hn);
        __syncthreads();
    }

    // ---- GRU epilogue ----
#pragma unroll
    for (int tm = 0; tm < 2; tm++) {
        int rbase = row0 + warp_m * 32 + tm * 16 + (lane >> 2);
#pragma unroll
        for (int half = 0; half < 2; half++) {
            int row_g = rbase + half * 8;
            if (row_g >= N_NODES) continue;
#pragma unroll
            for (int nt = 0; nt < 4; nt++) {
                int dim = d0 + warp_d * 32 + nt * 8 + (lane & 3) * 2;
                float o2[2];
#pragma unroll
                for (int e = 0; e < 2; e++) {
                    int cc = half * 2 + e;
                    int dd = dim + e;
                    float rs = acc_r[tm][nt][cc] + b_ih[dd] + b_hh[dd];
                    float zs = acc_z[tm][nt][cc] + b_ih[256 + dd] + b_hh[256 + dd];
                    float in_ = acc_n[tm][nt][cc] + b_ih[512 + dd];
                    float hn  = acc_hn[tm][nt][cc] + b_hh[512 + dd];
                    float r = 1.f / (1.f + expf(-rs));
                    float z = 1.f / (1.f + expf(-zs));
                    float nn = tanhf(in_ + r * hn);
                    float hold = h_in[(size_t)row_g * HID + dd];
                    o2[e] = (1.f - z) * nn + z * hold;
                }
                size_t ob = (size_t)row_g * HID + dim;
                *(float2*)(h_out + ob) = make_float2(o2[0], o2[1]);
                __nv_bfloat16 q0 = __float2bfloat16(o2[0]);
                __nv_bfloat16 q1 = __float2bfloat16(o2[1]);
                *(uint32_t*)(hh_out + ob) =
                    ((uint32_t)__bfloat16_as_ushort(q1) << 16) | __bfloat16_as_ushort(q0);
                *(uint32_t*)(hl_out + ob) =
                    pack_bf2(o2[0] - __bfloat162float(q0), o2[1] - __bfloat162float(q1));
            }
        }
    }
}

// ================= small kernels =================
__global__ void zero_kernel(float4* p, long n4) {
    long i = (long)blockIdx.x * blockDim.x + threadIdx.x;
    if (i < n4) p[i] = make_float4(0.f, 0.f, 0.f, 0.f);
}

__global__ void scatter_add_kernel(const float* __restrict__ h,
                                   const int* __restrict__ src,
                                   const int* __restrict__ dst,
                                   float* __restrict__ hs) {
    long idx = (long)blockIdx.x * blockDim.x + threadIdx.x;
    long e = idx >> 6;
    if (e >= N_EDGES) return;
    int q = (int)(idx & 63) << 2;
    int s = src[e];
    int d = dst[e];
    float4 v = *(const float4*)(h + (size_t)s * HID + q);
    atomicAdd((float4*)(hs + (size_t)d * HID + q), v);
}

// fp32 -> bf16 hi/lo pair (weights)
__global__ void conv_pair4(const float4* __restrict__ src, uint2* __restrict__ dh,
                           uint2* __restrict__ dl, long n4) {
    long i = (long)blockIdx.x * blockDim.x + threadIdx.x;
    if (i >= n4) return;
    uint2 uh, ul;
    split4(src[i], uh, ul);
    dh[i] = uh;
    dl[i] = ul;
}

__device__ __forceinline__ void split_store(float v, __nv_bfloat16* ph, __nv_bfloat16* pl) {
    __nv_bfloat16 h = __float2bfloat16(v);
    *ph = h;
    *pl = __float2bfloat16(v - __bfloat162float(h));
}

// ggc_w[s][k][n] -> wt[s][n][k]
__global__ void conv_ggc(const float* __restrict__ src, __nv_bfloat16* dh, __nv_bfloat16* dl) {
    int idx = blockIdx.x * blockDim.x + threadIdx.x;
    if (idx >= STEPS * 256 * 256) return;
    int s = idx >> 16, rem = idx & 65535;
    int nn = rem >> 8, kk = rem & 255;
    float v = src[(size_t)s * 65536 + kk * 256 + nn];
    split_store(v, dh + idx, dl + idx);
}
// Wa1[k(256)][n(128)] -> wa1t[n][k]
__global__ void conv_wa1(const float* __restrict__ src, __nv_bfloat16* dh, __nv_bfloat16* dl) {
    int idx = blockIdx.x * blockDim.x + threadIdx.x;
    if (idx >= 128 * 256) return;
    int nn = idx >> 8, kk = idx & 255;
    split_store(src[kk * 128 + nn], dh + idx, dl + idx);
}
// W_in[k(100)][n(256)] -> wint[n][k(128 padded)]
__global__ void conv_win(const float* __restrict__ src, __nv_bfloat16* dh, __nv_bfloat16* dl) {
    int idx = blockIdx.x * blockDim.x + threadIdx.x;
    if (idx >= 256 * 128) return;
    int nn = idx >> 7, kk = idx & 127;
    float v = (kk < IN_DIM) ? src[kk * 256 + nn] : 0.f;
    split_store(v, dh + idx, dl + idx);
}

// h = relu(h), emit bf16 split
__global__ void relu_h_kernel(float* __restrict__ h, __nv_bfloat16* __restrict__ hh,
                              __nv_bfloat16* __restrict__ hl) {
    long idx = (long)blockIdx.x * blockDim.x + threadIdx.x;
    if (idx >= (long)N_NODES * 64) return;
    size_t b = (size_t)idx << 2;
    float4 v = *(const float4*)(h + b);
    v.x = fmaxf(v.x, 0.f); v.y = fmaxf(v.y, 0.f);
    v.z = fmaxf(v.z, 0.f); v.w = fmaxf(v.w, 0.f);
    *(float4*)(h + b) = v;
    uint2 uh, ul;
    split4(v, uh, ul);
    *(uint2*)(hh + b) = uh;
    *(uint2*)(hl + b) = ul;
}

// a = sigmoid(t1 @ Wa2 + ba2)
__global__ void attn_a_kernel(const float* __restrict__ t1, const float* __restrict__ Wa2,
                              const float* __restrict__ ba2, float* __restrict__ a) {
    long idx = (long)blockIdx.x * blockDim.x + threadIdx.x;
    int warp = (int)(idx >> 5);
    int lane = (int)(idx & 31);
    if (warp >= N_NODES) return;
    float s = 0.f;
#pragma unroll
    for (int k = lane; k < HID / 2; k += 32) s += t1[(size_t)warp * (HID / 2) + k] * Wa2[k];
#pragma unroll
    for (int o = 16; o > 0; o >>= 1) s += __shfl_xor_sync(0xFFFFFFFFu, s, o);
    if (lane == 0) a[warp] = 1.f / (1.f + expf(-(s + ba2[0])));
}

__global__ void pool_kernel(const float* __restrict__ h, const float* __restrict__ a,
                            const int* __restrict__ batch, float* __restrict__ pool) {
    int g = blockIdx.x;
    int d = threadIdx.x;
    __shared__ int s_lo, s_hi;
    if (d == 0) {
        int lo = 0, hi = N_NODES;
        while (lo < hi) { int mid = (lo + hi) >> 1; if (batch[mid] < g) lo = mid + 1; else hi = mid; }
        s_lo = lo;
        lo = 0; hi = N_NODES;
        while (lo < hi) { int mid = (lo + hi) >> 1; if (batch[mid] < g + 1) lo = mid + 1; else hi = mid; }
        s_hi = lo;
    }
    __syncthreads();
    int lo = s_lo, hi = s_hi;
    float sum = 0.f, mx = 0.f;  // wx >= 0 so 0-init max matches ref
    for (int i = lo; i < hi; i++) {
        float w = h[(size_t)i * HID + d] * a[i];
        sum += w;
        mx = fmaxf(mx, w);
    }
    int cnt = hi - lo;
    pool[(size_t)g * 2 * HID + d] = sum / (float)(cnt > 1 ? cnt : 1);
    pool[(size_t)g * 2 * HID + HID + d] = (cnt > 0) ? mx : 0.f;
}

__global__ void classifier_kernel(const float* __restrict__ pool,
                                  const float* __restrict__ Wc1, const float* __restrict__ bc1,
                                  const float* __restrict__ Wc2, const float* __restrict__ bc2,
                                  const float* __restrict__ Wc3, const float* __restrict__ bc3,
                                  float* __restrict__ preds) {
    int g = blockIdx.x;
    int t = threadIdx.x;
    __shared__ float sg[2 * HID];
    __shared__ float t1[HID];
    __shared__ float t2[HID / 2];
    sg[t] = pool[(size_t)g * 2 * HID + t];
    sg[t + HID] = pool[(size_t)g * 2 * HID + HID + t];
    __syncthreads();
    {
        float acc = bc1[t];
        for (int k = 0; k < 2 * HID; k++) acc += sg[k] * Wc1[(size_t)k * HID + t];
        t1[t] = fmaxf(acc, 0.f);
    }
    __syncthreads();
    if (t < HID / 2) {
        float acc = bc2[t];
        for (int k = 0; k < HID; k++) acc += t1[k] * Wc2[(size_t)k * (HID / 2) + t];
        t2[t] = fmaxf(acc, 0.f);
    }
    __syncthreads();
    if (t < 2) {
        float acc = bc3[t];
        for (int k = 0; k < HID / 2; k++) acc += t2[k] * Wc3[(size_t)k * 2 + t];
        preds[g * 2 + t] = acc;
    }
}

// ================= launch =================
extern "C" void kernel_launch(void* const* d_in, const int* in_sizes, int n_in,
                              void* d_out, int out_size) {
    const float* x     = (const float*)d_in[0];
    const int*   edge  = (const int*)d_in[1];
    const int*   batch = (const int*)d_in[2];
    const float* W_in  = (const float*)d_in[3];
    const float* b_in  = (const float*)d_in[4];
    const float* ggc_w = (const float*)d_in[5];
    const float* W_ih  = (const float*)d_in[6];
    const float* W_hh  = (const float*)d_in[7];
    const float* b_ih  = (const float*)d_in[8];
    const float* b_hh  = (const float*)d_in[9];
    const float* Wa1   = (const float*)d_in[10];
    const float* ba1   = (const float*)d_in[11];
    const float* Wa2   = (const float*)d_in[12];
    const float* ba2   = (const float*)d_in[13];
    const float* Wc1   = (const float*)d_in[14];
    const float* bc1   = (const float*)d_in[15];
    const float* Wc2   = (const float*)d_in[16];
    const float* bc2   = (const float*)d_in[17];
    const float* Wc3   = (const float*)d_in[18];
    const float* bc3   = (const float*)d_in[19];

    float* out   = (float*)d_out;
    float* preds = out;
    float* a_out = out + N_GRAPHS * 2;

    float *h0, *h1, *hs, *t1, *pool;
    __nv_bfloat16 *hh0, *hl0, *hh1, *hl1, *ag_hi, *ag_lo;
    __nv_bfloat16 *wih_hi, *wih_lo, *whh_hi, *whh_lo, *wt_hi, *wt_lo, *wa1_hi, *wa1_lo, *win_hi, *win_lo;
    cudaGetSymbolAddress((void**)&h0, d_h0);
    cudaGetSymbolAddress((void**)&h1, d_h1);
    cudaGetSymbolAddress((void**)&hs, d_hs);
    cudaGetSymbolAddress((void**)&t1, d_t1);
    cudaGetSymbolAddress((void**)&pool, d_pool);
    cudaGetSymbolAddress((void**)&hh0, d_hh0);
    cudaGetSymbolAddress((void**)&hl0, d_hl0);
    cudaGetSymbolAddress((void**)&hh1, d_hh1);
    cudaGetSymbolAddress((void**)&hl1, d_hl1);
    cudaGetSymbolAddress((void**)&ag_hi, d_ag_hi);
    cudaGetSymbolAddress((void**)&ag_lo, d_ag_lo);
    cudaGetSymbolAddress((void**)&wih_hi, d_wih_hi);
    cudaGetSymbolAddress((void**)&wih_lo, d_wih_lo);
    cudaGetSymbolAddress((void**)&whh_hi, d_whh_hi);
    cudaGetSymbolAddress((void**)&whh_lo, d_whh_lo);
    cudaGetSymbolAddress((void**)&wt_hi, d_wt_hi);
    cudaGetSymbolAddress((void**)&wt_lo, d_wt_lo);
    cudaGetSymbolAddress((void**)&wa1_hi, d_wa1_hi);
    cudaGetSymbolAddress((void**)&wa1_lo, d_wa1_lo);
    cudaGetSymbolAddress((void**)&win_hi, d_win_hi);
    cudaGetSymbolAddress((void**)&win_lo, d_win_lo);

    float* hb[2] = {h0, h1};
    __nv_bfloat16* hhb[2] = {hh0, hh1};
    __nv_bfloat16* hlb[2] = {hl0, hl1};

    const int* src = edge;
    const int* dst = edge + N_EDGES;

    const int SMEM = 2 * 4 * (128 * 80);   // 81920 B
    const int GSMEM = 2 * 51200;           // 102400 B
    cudaFuncSetAttribute(mma_gemm<128, 100, true, true, true, true>,
                         cudaFuncAttributeMaxDynamicSharedMemorySize, SMEM);
    cudaFuncSetAttribute(mma_gemm<256, 256, true, false, true, false>,
                         cudaFuncAttributeMaxDynamicSharedMemorySize, SMEM);
    cudaFuncSetAttribute(mma_gemm<256, 256, false, true, false, true>,
                         cudaFuncAttributeMaxDynamicSharedMemorySize, SMEM);
    cudaFuncSetAttribute(gate_gru_kernel,
                         cudaFuncAttributeMaxDynamicSharedMemorySize, GSMEM);

    const int MT = (N_NODES + 127) / 128;  // 391

    // ---- weight conversions ----
    conv_pair4<<<(768 * 256 / 4 + 255) / 256, 256>>>((const float4*)W_ih, (uint2*)wih_hi, (uint2*)wih_lo, 768 * 256 / 4);
    conv_pair4<<<(768 * 256 / 4 + 255) / 256, 256>>>((const float4*)W_hh, (uint2*)whh_hi, (uint2*)whh_lo, 768 * 256 / 4);
    conv_ggc<<<(STEPS * 65536 + 255) / 256, 256>>>(ggc_w, wt_hi, wt_lo);
    conv_wa1<<<(128 * 256 + 255) / 256, 256>>>(Wa1, wa1_hi, wa1_lo);
    conv_win<<<(256 * 128 + 255) / 256, 256>>>(W_in, win_hi, win_lo);

    // ---- input projection: h0 = relu(x @ W_in + b_in), fp32 A fused split ----
    mma_gemm<128, 100, true, true, true, true><<<dim3(2, MT), 256, SMEM>>>(
        x, nullptr, win_hi, win_lo, b_in, hb[0], hhb[0], hlb[0], N_NODES, N_NODES, HID);

    long n4_hs = (long)N_NODES * HID / 4;
    for (int s = 0; s < STEPS; s++) {
        int p = s & 1;
        zero_kernel<<<(unsigned)((n4_hs + 255) / 256), 256>>>((float4*)hs, n4_hs);
        {
            long tot = (long)N_EDGES * 64;
            scatter_add_kernel<<<(unsigned)((tot + 255) / 256), 256>>>(hb[p], src, dst, hs);
        }
        // agg = hs @ w[s]  (fp32 A fused split -> bf16 pair out)
        mma_gemm<256, 256, true, false, true, false><<<dim3(2, MT), 256, SMEM>>>(
            hs, nullptr, wt_hi + (size_t)s * 65536, wt_lo + (size_t)s * 65536,
            nullptr, nullptr, ag_hi, ag_lo, N_NODES, MPAD, HID);
        // fused gate GEMMs + GRU: h[p^1] = GRU(agg, h[p])
        gate_gru_kernel<<<dim3(4, MT), 256, GSMEM>>>(
            ag_hi, ag_lo, hhb[p], hlb[p],
            wih_hi, wih_lo, whh_hi, whh_lo, b_ih, b_hh,
            hb[p], hb[p ^ 1], hhb[p ^ 1], hlb[p ^ 1]);
    }

    const int F = STEPS & 1;  // final buffer index = 1
    {
        long tot = (long)N_NODES * 64;
        relu_h_kernel<<<(unsigned)((tot + 255) / 256), 256>>>(hb[F], hhb[F], hlb[F]);
    }

    // attention: t1 = relu(h @ Wa1 + ba1)
    mma_gemm<256, 256, false, true, false, true><<<dim3(1, MT), 256, SMEM>>>(
        hhb[F], hlb[F], wa1_hi, wa1_lo, ba1, t1, nullptr, nullptr, N_NODES, MPAD, HID / 2);
    {
        long tot = (long)N_NODES * 32;
        attn_a_kernel<<<(unsigned)((tot + 255) / 256), 256>>>(t1, Wa2, ba2, a_out);
    }

    pool_kernel<<<N_GRAPHS, HID>>>(hb[F], a_out, batch, pool);
    classifier_kernel<<<N_GRAPHS, 256>>>(pool, Wc1, bc1, Wc2, bc2, Wc3, bc3, preds);
}

// round 11
// speedup vs baseline: 1.3564x; 1.3564x over previous
#include <cuda_runtime.h>
#include <cuda_bf16.h>
#include <cstdint>
#include <math.h>

#define N_NODES 50000
#define MPAD    50048   // multiple of 128; pad rows stay zero (.bss)
#define N_EDGES 800000
#define N_GRAPHS 128
#define IN_DIM  100
#define HID     256
#define STEPS   5

// ---------------- scratch (device globals; zero-initialized, no allocation) ----
__device__ float d_h [MPAD * HID];
__device__ float d_hs[MPAD * HID];          // gathered (sum h[src]) per dst
__device__ float d_gi[(size_t)N_NODES * 3 * HID];
__device__ float d_gh[(size_t)N_NODES * 3 * HID];
__device__ float d_t1[(size_t)N_NODES * (HID / 2)];
__device__ float d_pool[N_GRAPHS * 2 * HID];

__device__ __nv_bfloat16 d_h_hi [MPAD * HID], d_h_lo [MPAD * HID];
__device__ __nv_bfloat16 d_hs_hi[MPAD * HID], d_hs_lo[MPAD * HID];
__device__ __nv_bfloat16 d_ag_hi[MPAD * HID], d_ag_lo[MPAD * HID];
__device__ __nv_bfloat16 d_x_hi [MPAD * 128], d_x_lo [MPAD * 128];

__device__ __nv_bfloat16 d_wih_hi[768 * 256], d_wih_lo[768 * 256];
__device__ __nv_bfloat16 d_whh_hi[768 * 256], d_whh_lo[768 * 256];
__device__ __nv_bfloat16 d_wt_hi [STEPS * 256 * 256], d_wt_lo [STEPS * 256 * 256];
__device__ __nv_bfloat16 d_wa1_hi[128 * 256], d_wa1_lo[128 * 256];
__device__ __nv_bfloat16 d_win_hi[256 * 128], d_win_lo[256 * 128];

// ---------------- CSR-by-destination (built once per call) ----------------
__device__ int d_deg [N_NODES];
__device__ int d_fill[N_NODES];
__device__ int d_offs[N_NODES + 1];
__device__ int d_eidx[N_EDGES];     // src node ids bucketed by dst

// ================= PTX helpers (sm_80-baseline only) =================
__device__ __forceinline__ uint32_t smem_u32(const void* p) {
    uint32_t a;
    asm("{ .reg .u64 t; cvta.to.shared.u64 t, %1; cvt.u32.u64 %0, t; }" : "=r"(a) : "l"(p));
    return a;
}
__device__ __forceinline__ void cp16(uint32_t s, const void* g) {
    asm volatile("cp.async.cg.shared.global [%0], [%1], 16;" :: "r"(s), "l"(g));
}
#define CP_COMMIT() asm volatile("cp.async.commit_group;" ::: "memory")
#define CP_WAIT(N)  asm volatile("cp.async.wait_group %0;" :: "n"(N) : "memory")

__device__ __forceinline__ void ldm4(uint32_t& r0, uint32_t& r1, uint32_t& r2, uint32_t& r3,
                                     uint32_t a) {
    asm volatile("ldmatrix.sync.aligned.m8n8.x4.shared.b16 {%0,%1,%2,%3}, [%4];"
                 : "=r"(r0), "=r"(r1), "=r"(r2), "=r"(r3) : "r"(a));
}
__device__ __forceinline__ void mma_bf16(float* c, const uint32_t* a, const uint32_t* b) {
    asm volatile(
        "mma.sync.aligned.m16n8k16.row.col.f32.bf16.bf16.f32 "
        "{%0,%1,%2,%3}, {%4,%5,%6,%7}, {%8,%9}, {%0,%1,%2,%3};"
        : "+f"(c[0]), "+f"(c[1]), "+f"(c[2]), "+f"(c[3])
        : "r"(a[0]), "r"(a[1]), "r"(a[2]), "r"(a[3]), "r"(b[0]), "r"(b[1]));
}
__device__ __forceinline__ uint32_t pack_bf2(float a, float b) {
    __nv_bfloat16 x = __float2bfloat16(a), y = __float2bfloat16(b);
    return ((uint32_t)__bfloat16_as_ushort(y) << 16) | (uint32_t)__bfloat16_as_ushort(x);
}

// ================= mma.sync GEMM: C[M, Ntot] = A[M, K] @ B[Ntot, K]^T ==========
// A as bf16 hi/lo [MPAD, K] (K-contig), B as bf16 hi/lo [Ntot, K] (K-contig).
// Split product: AhBh + AhBl + AlBh, fp32 accumulation.
// CTA tile 128x128, 8 warps (warp_m 0..3 x warp_n 0..1), warp tile 32x64.
// K chunk 32, cp.async double-buffered. Smem row stride 80B (conflict-free ldmatrix).
template <int KTOT, bool WF32, bool WBF16, bool RELU>
__global__ __launch_bounds__(256) void mma_gemm(
    const __nv_bfloat16* __restrict__ Ah, const __nv_bfloat16* __restrict__ Al,
    const __nv_bfloat16* __restrict__ Bh, const __nv_bfloat16* __restrict__ Bl,
    const float* __restrict__ bias,
    float* __restrict__ Cf, __nv_bfloat16* __restrict__ Cbh, __nv_bfloat16* __restrict__ Cbl,
    int M, int Ntot)
{
    constexpr int CH = KTOT / 32;
    constexpr int RSTRIDE = 80;          // bytes per 32-element bf16 row (64B data + 16B pad)
    constexpr int MAT = 128 * RSTRIDE;   // 10240 B per matrix per stage
    extern __shared__ char smem[];
    const uint32_t sb = smem_u32(smem);

    const int tid = threadIdx.x;
    const int wid = tid >> 5, lane = tid & 31;
    const int warp_m = wid & 3, warp_n = wid >> 2;
    const int row0 = blockIdx.y * 128;
    const int ncol0 = blockIdx.x * 128;

    float acc[2][8][4];
#pragma unroll
    for (int tm = 0; tm < 2; tm++)
#pragma unroll
        for (int nt = 0; nt < 8; nt++)
#pragma unroll
            for (int c = 0; c < 4; c++) acc[tm][nt][c] = 0.f;

    auto load_stage = [&](int c, int st) {
        const int k0 = c * 32;
        const uint32_t base = sb + st * (4 * MAT);
#pragma unroll
        for (int i = 0; i < 2; i++) {
            int l = tid + i * 256;       // 512 uint4 per matrix
            int row = l >> 2, q = l & 3;
            uint32_t so = (uint32_t)(row * RSTRIDE + q * 16);
            size_t ea = (size_t)(row0 + row) * KTOT + k0 + q * 8;
            size_t eb = (size_t)(ncol0 + row) * KTOT + k0 + q * 8;
            cp16(base + so,           Ah + ea);
            cp16(base + MAT + so,     Al + ea);
            cp16(base + 2 * MAT + so, Bh + eb);
            cp16(base + 3 * MAT + so, Bl + eb);
        }
    };

    load_stage(0, 0);
    CP_COMMIT();

    const int ar = (lane & 7) + ((lane >> 3) & 1) * 8;   // A m-row within 16
    const int akh = lane >> 4;                            // A k-half
    const int bn = (lane >> 4);                           // B tile within pair
    const int bk = (lane >> 3) & 1;                       // B k-half

    for (int c = 0; c < CH; c++) {
        const int st = c & 1;
        if (c + 1 < CH) {
            load_stage(c + 1, st ^ 1);
            CP_COMMIT();
            CP_WAIT(1);
        } else {
            CP_WAIT(0);
        }
        __syncthreads();

        const uint32_t base = sb + st * (4 * MAT);
#pragma unroll
        for (int j = 0; j < 2; j++) {    // two k16 per chunk
            uint32_t ah[2][4], al[2][4];
#pragma unroll
            for (int tm = 0; tm < 2; tm++) {
                uint32_t ao = base + (uint32_t)((warp_m * 32 + tm * 16 + ar) * RSTRIDE +
                                                j * 32 + akh * 16);
                ldm4(ah[tm][0], ah[tm][1], ah[tm][2], ah[tm][3], ao);
                ldm4(al[tm][0], al[tm][1], al[tm][2], al[tm][3], ao + MAT);
            }
            uint32_t bh[4][4], bl[4][4];
#pragma unroll
            for (int q = 0; q < 4; q++) {
                int nrow = warp_n * 64 + (2 * q + bn) * 8 + (lane & 7);
                uint32_t bo = base + 2 * MAT +
                              (uint32_t)(nrow * RSTRIDE + j * 32 + bk * 16);
                ldm4(bh[q][0], bh[q][1], bh[q][2], bh[q][3], bo);
                ldm4(bl[q][0], bl[q][1], bl[q][2], bl[q][3], bo + MAT);
            }
#pragma unroll
            for (int tm = 0; tm < 2; tm++)
#pragma unroll
                for (int nt = 0; nt < 8; nt++) {
                    int q = nt >> 1, o = (nt & 1) * 2;
                    mma_bf16(acc[tm][nt], ah[tm], &bh[q][o]);
                    mma_bf16(acc[tm][nt], ah[tm], &bl[q][o]);
                    mma_bf16(acc[tm][nt], al[tm], &bh[q][o]);
                }
        }
        __syncthreads();
    }

    // ---- epilogue ----
#pragma unroll
    for (int tm = 0; tm < 2; tm++) {
        int rbase = row0 + warp_m * 32 + tm * 16 + (lane >> 2);
#pragma unroll
        for (int half = 0; half < 2; half++) {
            int row_g = rbase + half * 8;
            if (row_g >= M) continue;
#pragma unroll
            for (int nt = 0; nt < 8; nt++) {
                int col = ncol0 + warp_n * 64 + nt * 8 + (lane & 3) * 2;
                float v0 = acc[tm][nt][half * 2 + 0];
                float v1 = acc[tm][nt][half * 2 + 1];
                if (bias) { v0 += bias[col]; v1 += bias[col + 1]; }
                if (RELU) { v0 = fmaxf(v0, 0.f); v1 = fmaxf(v1, 0.f); }
                if (WF32) {
                    float2 w = make_float2(v0, v1);
                    *(float2*)(Cf + (size_t)row_g * Ntot + col) = w;
                }
                if (WBF16) {
                    __nv_bfloat16 h0 = __float2bfloat16(v0);
                    __nv_bfloat16 h1 = __float2bfloat16(v1);
                    float l0 = v0 - __bfloat162float(h0);
                    float l1 = v1 - __bfloat162float(h1);
                    *(uint32_t*)(Cbh + (size_t)row_g * Ntot + col) =
                        ((uint32_t)__bfloat16_as_ushort(h1) << 16) | __bfloat16_as_ushort(h0);
                    *(uint32_t*)(Cbl + (size_t)row_g * Ntot + col) = pack_bf2(l0, l1);
                }
            }
        }
    }
}

// ================= CSR build (once per call) =================
__global__ void zero_csr_kernel(int* deg, int* fill) {
    int i = blockIdx.x * blockDim.x + threadIdx.x;
    if (i < N_NODES) { deg[i] = 0; fill[i] = 0; }
}
__global__ void hist_kernel(const int* __restrict__ dst, int* __restrict__ deg) {
    int e = blockIdx.x * blockDim.x + threadIdx.x;
    if (e < N_EDGES) atomicAdd(&deg[dst[e]], 1);
}
// single-block exclusive scan over 50000 degrees -> offs[0..N_NODES]
__global__ __launch_bounds__(1024) void scan_kernel(const int* __restrict__ deg,
                                                    int* __restrict__ offs) {
    __shared__ int part[1024];
    const int tid = threadIdx.x;
    const int per = (N_NODES + 1023) / 1024;  // 49
    int s0 = tid * per;
    int s1 = s0 + per; if (s1 > N_NODES) s1 = N_NODES;
    int sum = 0;
    for (int i = s0; i < s1; i++) sum += deg[i];
    part[tid] = sum;
    __syncthreads();
    for (int off = 1; off < 1024; off <<= 1) {
        int v = 0;
        if (tid >= off) v = part[tid - off];
        __syncthreads();
        if (tid >= off) part[tid] += v;
        __syncthreads();
    }
    int run = (tid == 0) ? 0 : part[tid - 1];
    for (int i = s0; i < s1; i++) { offs[i] = run; run += deg[i]; }
    if (tid == 1023) offs[N_NODES] = run;
}
__global__ void fill_kernel(const int* __restrict__ src, const int* __restrict__ dst,
                            const int* __restrict__ offs, int* __restrict__ fill,
                            int* __restrict__ eidx) {
    int e = blockIdx.x * blockDim.x + threadIdx.x;
    if (e >= N_EDGES) return;
    int d = dst[e];
    int pos = offs[d] + atomicAdd(&fill[d], 1);
    eidx[pos] = src[e];
}

// ================= atomic-free gather: hs[n] = sum_{e: dst=n} h[src[e]] =======
__global__ __launch_bounds__(128) void gather_kernel(
    const float* __restrict__ h, const int* __restrict__ offs,
    const int* __restrict__ eidx, float* __restrict__ hs) {
    int node = blockIdx.x;
    int t = threadIdx.x;                   // 128 threads, float2 each
    int lo = offs[node], hi = offs[node + 1];
    float2 acc = make_float2(0.f, 0.f);
    for (int j = lo; j < hi; j++) {
        int s = __ldg(eidx + j);
        float2 v = *(const float2*)(h + (size_t)s * HID + t * 2);
        acc.x += v.x; acc.y += v.y;
    }
    *(float2*)(hs + (size_t)node * HID + t * 2) = acc;
}

// ================= small kernels =================
// fp32 -> bf16 hi/lo pair (vectorized)
__global__ void conv_pair4(const float4* __restrict__ src, uint2* __restrict__ dh,
                           uint2* __restrict__ dl, long n4) {
    long i = (long)blockIdx.x * blockDim.x + threadIdx.x;
    if (i >= n4) return;
    float4 v = src[i];
    __nv_bfloat16 h0 = __float2bfloat16(v.x), h1 = __float2bfloat16(v.y);
    __nv_bfloat16 h2 = __float2bfloat16(v.z), h3 = __float2bfloat16(v.w);
    uint2 uh, ul;
    uh.x = ((uint32_t)__bfloat16_as_ushort(h1) << 16) | __bfloat16_as_ushort(h0);
    uh.y = ((uint32_t)__bfloat16_as_ushort(h3) << 16) | __bfloat16_as_ushort(h2);
    ul.x = pack_bf2(v.x - __bfloat162float(h0), v.y - __bfloat162float(h1));
    ul.y = pack_bf2(v.z - __bfloat162float(h2), v.w - __bfloat162float(h3));
    dh[i] = uh;
    dl[i] = ul;
}

__device__ __forceinline__ void split_store(float v, __nv_bfloat16* ph, __nv_bfloat16* pl) {
    __nv_bfloat16 h = __float2bfloat16(v);
    *ph = h;
    *pl = __float2bfloat16(v - __bfloat162float(h));
}

// ggc_w[s][k][n] -> wt[s][n][k]
__global__ void conv_ggc(const float* __restrict__ src, __nv_bfloat16* dh, __nv_bfloat16* dl) {
    int idx = blockIdx.x * blockDim.x + threadIdx.x;
    if (idx >= STEPS * 256 * 256) return;
    int s = idx >> 16, rem = idx & 65535;
    int nn = rem >> 8, kk = rem & 255;
    float v = src[(size_t)s * 65536 + kk * 256 + nn];
    split_store(v, dh + idx, dl + idx);
}
// Wa1[k(256)][n(128)] -> wa1t[n][k]
__global__ void conv_wa1(const float* __restrict__ src, __nv_bfloat16* dh, __nv_bfloat16* dl) {
    int idx = blockIdx.x * blockDim.x + threadIdx.x;
    if (idx >= 128 * 256) return;
    int nn = idx >> 8, kk = idx & 255;
    split_store(src[kk * 128 + nn], dh + idx, dl + idx);
}
// W_in[k(100)][n(256)] -> wint[n][k(128 padded)]
__global__ void conv_win(const float* __restrict__ src, __nv_bfloat16* dh, __nv_bfloat16* dl) {
    int idx = blockIdx.x * blockDim.x + threadIdx.x;
    if (idx >= 256 * 128) return;
    int nn = idx >> 7, kk = idx & 127;
    float v = (kk < IN_DIM) ? src[kk * 256 + nn] : 0.f;
    split_store(v, dh + idx, dl + idx);
}
// x[r][100] -> x_hi/lo[r][128 padded]
__global__ void conv_x(const float* __restrict__ x, __nv_bfloat16* dh, __nv_bfloat16* dl) {
    long idx = (long)blockIdx.x * blockDim.x + threadIdx.x;
    if (idx >= (long)N_NODES * 128) return;
    int r = (int)(idx >> 7), k = (int)(idx & 127);
    float v = (k < IN_DIM) ? x[(size_t)r * IN_DIM + k] : 0.f;
    split_store(v, dh + idx, dl + idx);
}

// GRU elementwise (+biases), fused bf16-split emission of new h
__global__ void gru_kernel(const float* __restrict__ gi, const float* __restrict__ gh,
                           const float* __restrict__ b_ih, const float* __restrict__ b_hh,
                           float* __restrict__ h, __nv_bfloat16* __restrict__ hh,
                           __nv_bfloat16* __restrict__ hl) {
    long idx = (long)blockIdx.x * blockDim.x + threadIdx.x;
    if (idx >= (long)N_NODES * 64) return;
    int n = (int)(idx >> 6);
    int d = (int)(idx & 63) << 2;
    size_t b3 = (size_t)n * 768 + d;
    float4 ir = *(const float4*)(gi + b3);
    float4 iz = *(const float4*)(gi + b3 + 256);
    float4 in_ = *(const float4*)(gi + b3 + 512);
    float4 hr = *(const float4*)(gh + b3);
    float4 hz = *(const float4*)(gh + b3 + 256);
    float4 hn = *(const float4*)(gh + b3 + 512);
    float4 bir = *(const float4*)(b_ih + d);
    float4 biz = *(const float4*)(b_ih + 256 + d);
    float4 bin_ = *(const float4*)(b_ih + 512 + d);
    float4 bhr = *(const float4*)(b_hh + d);
    float4 bhz = *(const float4*)(b_hh + 256 + d);
    float4 bhn = *(const float4*)(b_hh + 512 + d);
    size_t hb = (size_t)n * HID + d;
    float4 hv = *(const float4*)(h + hb);
    float o[4];
#pragma unroll
    for (int c = 0; c < 4; c++) {
        float xir = ((const float*)&ir)[c] + ((const float*)&bir)[c];
        float xiz = ((const float*)&iz)[c] + ((const float*)&biz)[c];
        float xin = ((const float*)&in_)[c] + ((const float*)&bin_)[c];
        float xhr = ((const float*)&hr)[c] + ((const float*)&bhr)[c];
        float xhz = ((const float*)&hz)[c] + ((const float*)&bhz)[c];
        float xhn = ((const float*)&hn)[c] + ((const float*)&bhn)[c];
        float hold = ((const float*)&hv)[c];
        float r = 1.f / (1.f + expf(-(xir + xhr)));
        float z = 1.f / (1.f + expf(-(xiz + xhz)));
        float nn = tanhf(xin + r * xhn);
        o[c] = (1.f - z) * nn + z * hold;
    }
    *(float4*)(h + hb) = make_float4(o[0], o[1], o[2], o[3]);
    __nv_bfloat16 q0 = __float2bfloat16(o[0]), q1 = __float2bfloat16(o[1]);
    __nv_bfloat16 q2 = __float2bfloat16(o[2]), q3 = __float2bfloat16(o[3]);
    uint2 uh, ul;
    uh.x = ((uint32_t)__bfloat16_as_ushort(q1) << 16) | __bfloat16_as_ushort(q0);
    uh.y = ((uint32_t)__bfloat16_as_ushort(q3) << 16) | __bfloat16_as_ushort(q2);
    ul.x = pack_bf2(o[0] - __bfloat162float(q0), o[1] - __bfloat162float(q1));
    ul.y = pack_bf2(o[2] - __bfloat162float(q2), o[3] - __bfloat162float(q3));
    *(uint2*)(hh + hb) = uh;
    *(uint2*)(hl + hb) = ul;
}

// h = relu(h), re-emit bf16 split
__global__ void relu_h_kernel(float* __restrict__ h, __nv_bfloat16* __restrict__ hh,
                              __nv_bfloat16* __restrict__ hl) {
    long idx = (long)blockIdx.x * blockDim.x + threadIdx.x;
    if (idx >= (long)N_NODES * 64) return;
    size_t b = (size_t)idx << 2;
    float4 v = *(const float4*)(h + b);
    v.x = fmaxf(v.x, 0.f); v.y = fmaxf(v.y, 0.f);
    v.z = fmaxf(v.z, 0.f); v.w = fmaxf(v.w, 0.f);
    *(float4*)(h + b) = v;
    __nv_bfloat16 q0 = __float2bfloat16(v.x), q1 = __float2bfloat16(v.y);
    __nv_bfloat16 q2 = __float2bfloat16(v.z), q3 = __float2bfloat16(v.w);
    uint2 uh, ul;
    uh.x = ((uint32_t)__bfloat16_as_ushort(q1) << 16) | __bfloat16_as_ushort(q0);
    uh.y = ((uint32_t)__bfloat16_as_ushort(q3) << 16) | __bfloat16_as_ushort(q2);
    ul.x = pack_bf2(v.x - __bfloat162float(q0), v.y - __bfloat162float(q1));
    ul.y = pack_bf2(v.z - __bfloat162float(q2), v.w - __bfloat162float(q3));
    *(uint2*)(hh + b) = uh;
    *(uint2*)(hl + b) = ul;
}

// a = sigmoid(t1 @ Wa2 + ba2)
__global__ void attn_a_kernel(const float* __restrict__ t1, const float* __restrict__ Wa2,
                              const float* __restrict__ ba2, float* __restrict__ a) {
    long idx = (long)blockIdx.x * blockDim.x + threadIdx.x;
    int warp = (int)(idx >> 5);
    int lane = (int)(idx & 31);
    if (warp >= N_NODES) return;
    float s = 0.f;
#pragma unroll
    for (int k = lane; k < HID / 2; k += 32) s += t1[(size_t)warp * (HID / 2) + k] * Wa2[k];
#pragma unroll
    for (int o = 16; o > 0; o >>= 1) s += __shfl_xor_sync(0xFFFFFFFFu, s, o);
    if (lane == 0) a[warp] = 1.f / (1.f + expf(-(s + ba2[0])));
}

__global__ void pool_kernel(const float* __restrict__ h, const float* __restrict__ a,
                            const int* __restrict__ batch, float* __restrict__ pool) {
    int g = blockIdx.x;
    int d = threadIdx.x;
    __shared__ int s_lo, s_hi;
    if (d == 0) {
        int lo = 0, hi = N_NODES;
        while (lo < hi) { int mid = (lo + hi) >> 1; if (batch[mid] < g) lo = mid + 1; else hi = mid; }
        s_lo = lo;
        lo = 0; hi = N_NODES;
        while (lo < hi) { int mid = (lo + hi) >> 1; if (batch[mid] < g + 1) lo = mid + 1; else hi = mid; }
        s_hi = lo;
    }
    __syncthreads();
    int lo = s_lo, hi = s_hi;
    float sum = 0.f, mx = 0.f;  // wx >= 0 so 0-init max matches ref
    for (int i = lo; i < hi; i++) {
        float w = h[(size_t)i * HID + d] * a[i];
        sum += w;
        mx = fmaxf(mx, w);
    }
    int cnt = hi - lo;
    pool[(size_t)g * 2 * HID + d] = sum / (float)(cnt > 1 ? cnt : 1);
    pool[(size_t)g * 2 * HID + HID + d] = (cnt > 0) ? mx : 0.f;
}

__global__ void classifier_kernel(const float* __restrict__ pool,
                                  const float* __restrict__ Wc1, const float* __restrict__ bc1,
                                  const float* __restrict__ Wc2, const float* __restrict__ bc2,
                                  const float* __restrict__ Wc3, const float* __restrict__ bc3,
                                  float* __restrict__ preds) {
    int g = blockIdx.x;
    int t = threadIdx.x;
    __shared__ float sg[2 * HID];
    __shared__ float t1[HID];
    __shared__ float t2[HID / 2];
    sg[t] = pool[(size_t)g * 2 * HID + t];
    sg[t + HID] = pool[(size_t)g * 2 * HID + HID + t];
    __syncthreads();
    {
        float acc = bc1[t];
        for (int k = 0; k < 2 * HID; k++) acc += sg[k] * Wc1[(size_t)k * HID + t];
        t1[t] = fmaxf(acc, 0.f);
    }
    __syncthreads();
    if (t < HID / 2) {
        float acc = bc2[t];
        for (int k = 0; k < HID; k++) acc += t1[k] * Wc2[(size_t)k * (HID / 2) + t];
        t2[t] = fmaxf(acc, 0.f);
    }
    __syncthreads();
    if (t < 2) {
        float acc = bc3[t];
        for (int k = 0; k < HID / 2; k++) acc += t2[k] * Wc3[(size_t)k * 2 + t];
        preds[g * 2 + t] = acc;
    }
}

// ================= launch =================
extern "C" void kernel_launch(void* const* d_in, const int* in_sizes, int n_in,
                              void* d_out, int out_size) {
    const float* x     = (const float*)d_in[0];
    const int*   edge  = (const int*)d_in[1];
    const int*   batch = (const int*)d_in[2];
    const float* W_in  = (const float*)d_in[3];
    const float* b_in  = (const float*)d_in[4];
    const float* ggc_w = (const float*)d_in[5];
    const float* W_ih  = (const float*)d_in[6];
    const float* W_hh  = (const float*)d_in[7];
    const float* b_ih  = (const float*)d_in[8];
    const float* b_hh  = (const float*)d_in[9];
    const float* Wa1   = (const float*)d_in[10];
    const float* ba1   = (const float*)d_in[11];
    const float* Wa2   = (const float*)d_in[12];
    const float* ba2   = (const float*)d_in[13];
    const float* Wc1   = (const float*)d_in[14];
    const float* bc1   = (const float*)d_in[15];
    const float* Wc2   = (const float*)d_in[16];
    const float* bc2   = (const float*)d_in[17];
    const float* Wc3   = (const float*)d_in[18];
    const float* bc3   = (const float*)d_in[19];

    float* out   = (float*)d_out;
    float* preds = out;
    float* a_out = out + N_GRAPHS * 2;

    float *h, *hs, *gi, *gh, *t1, *pool;
    __nv_bfloat16 *h_hi, *h_lo, *hs_hi, *hs_lo, *ag_hi, *ag_lo, *x_hi, *x_lo;
    __nv_bfloat16 *wih_hi, *wih_lo, *whh_hi, *whh_lo, *wt_hi, *wt_lo, *wa1_hi, *wa1_lo, *win_hi, *win_lo;
    int *deg, *fill, *offs, *eidx;
    cudaGetSymbolAddress((void**)&h, d_h);
    cudaGetSymbolAddress((void**)&hs, d_hs);
    cudaGetSymbolAddress((void**)&gi, d_gi);
    cudaGetSymbolAddress((void**)&gh, d_gh);
    cudaGetSymbolAddress((void**)&t1, d_t1);
    cudaGetSymbolAddress((void**)&pool, d_pool);
    cudaGetSymbolAddress((void**)&h_hi, d_h_hi);
    cudaGetSymbolAddress((void**)&h_lo, d_h_lo);
    cudaGetSymbolAddress((void**)&hs_hi, d_hs_hi);
    cudaGetSymbolAddress((void**)&hs_lo, d_hs_lo);
    cudaGetSymbolAddress((void**)&ag_hi, d_ag_hi);
    cudaGetSymbolAddress((void**)&ag_lo, d_ag_lo);
    cudaGetSymbolAddress((void**)&x_hi, d_x_hi);
    cudaGetSymbolAddress((void**)&x_lo, d_x_lo);
    cudaGetSymbolAddress((void**)&wih_hi, d_wih_hi);
    cudaGetSymbolAddress((void**)&wih_lo, d_wih_lo);
    cudaGetSymbolAddress((void**)&whh_hi, d_whh_hi);
    cudaGetSymbolAddress((void**)&whh_lo, d_whh_lo);
    cudaGetSymbolAddress((void**)&wt_hi, d_wt_hi);
    cudaGetSymbolAddress((void**)&wt_lo, d_wt_lo);
    cudaGetSymbolAddress((void**)&wa1_hi, d_wa1_hi);
    cudaGetSymbolAddress((void**)&wa1_lo, d_wa1_lo);
    cudaGetSymbolAddress((void**)&win_hi, d_win_hi);
    cudaGetSymbolAddress((void**)&win_lo, d_win_lo);
    cudaGetSymbolAddress((void**)&deg, d_deg);
    cudaGetSymbolAddress((void**)&fill, d_fill);
    cudaGetSymbolAddress((void**)&offs, d_offs);
    cudaGetSymbolAddress((void**)&eidx, d_eidx);

    const int* src = edge;
    const int* dst = edge + N_EDGES;

    const int SMEM = 2 * 4 * (128 * 80);  // 81920 B
    cudaFuncSetAttribute(mma_gemm<128, true, true, true>,
                         cudaFuncAttributeMaxDynamicSharedMemorySize, SMEM);
    cudaFuncSetAttribute(mma_gemm<256, false, true, false>,
                         cudaFuncAttributeMaxDynamicSharedMemorySize, SMEM);
    cudaFuncSetAttribute(mma_gemm<256, true, false, false>,
                         cudaFuncAttributeMaxDynamicSharedMemorySize, SMEM);
    cudaFuncSetAttribute(mma_gemm<256, true, false, true>,
                         cudaFuncAttributeMaxDynamicSharedMemorySize, SMEM);

    const int MT = (N_NODES + 127) / 128;  // 391

    // ---- CSR build (graph constant within a call) ----
    zero_csr_kernel<<<(N_NODES + 255) / 256, 256>>>(deg, fill);
    hist_kernel<<<(N_EDGES + 255) / 256, 256>>>(dst, deg);
    scan_kernel<<<1, 1024>>>(deg, offs);
    fill_kernel<<<(N_EDGES + 255) / 256, 256>>>(src, dst, offs, fill, eidx);

    // ---- weight / input conversions ----
    conv_pair4<<<(768 * 256 / 4 + 255) / 256, 256>>>((const float4*)W_ih, (uint2*)wih_hi, (uint2*)wih_lo, 768 * 256 / 4);
    conv_pair4<<<(768 * 256 / 4 + 255) / 256, 256>>>((const float4*)W_hh, (uint2*)whh_hi, (uint2*)whh_lo, 768 * 256 / 4);
    conv_ggc<<<(STEPS * 65536 + 255) / 256, 256>>>(ggc_w, wt_hi, wt_lo);
    conv_wa1<<<(128 * 256 + 255) / 256, 256>>>(Wa1, wa1_hi, wa1_lo);
    conv_win<<<(256 * 128 + 255) / 256, 256>>>(W_in, win_hi, win_lo);
    {
        long tot = (long)N_NODES * 128;
        conv_x<<<(unsigned)((tot + 255) / 256), 256>>>(x, x_hi, x_lo);
    }

    // ---- input projection: h = relu(x @ W_in + b_in), fused bf16 split ----
    mma_gemm<128, true, true, true><<<dim3(2, MT), 256, SMEM>>>(
        x_hi, x_lo, win_hi, win_lo, b_in, h, h_hi, h_lo, N_NODES, HID);

    long n4_hs = (long)N_NODES * HID / 4;
    for (int s = 0; s < STEPS; s++) {
        // hs[n] = sum over in-edges of h[src] (atomic-free CSR gather)
        gather_kernel<<<N_NODES, 128>>>(h, offs, eidx, hs);
        conv_pair4<<<(unsigned)((n4_hs + 255) / 256), 256>>>((const float4*)hs, (uint2*)hs_hi, (uint2*)hs_lo, n4_hs);
        // agg = hs @ w[s]  (bf16-split output only)
        mma_gemm<256, false, true, false><<<dim3(2, MT), 256, SMEM>>>(
            hs_hi, hs_lo, wt_hi + (size_t)s * 65536, wt_lo + (size_t)s * 65536,
            nullptr, nullptr, ag_hi, ag_lo, N_NODES, HID);
        // gi = agg @ W_ih^T ; gh = h @ W_hh^T
        mma_gemm<256, true, false, false><<<dim3(6, MT), 256, SMEM>>>(
            ag_hi, ag_lo, wih_hi, wih_lo, nullptr, gi, nullptr, nullptr, N_NODES, 3 * HID);
        mma_gemm<256, true, false, false><<<dim3(6, MT), 256, SMEM>>>(
            h_hi, h_lo, whh_hi, whh_lo, nullptr, gh, nullptr, nullptr, N_NODES, 3 * HID);
        {
            long tot = (long)N_NODES * 64;
            gru_kernel<<<(unsigned)((tot + 255) / 256), 256>>>(gi, gh, b_ih, b_hh, h, h_hi, h_lo);
        }
    }

    {
        long tot = (long)N_NODES * 64;
        relu_h_kernel<<<(unsigned)((tot + 255) / 256), 256>>>(h, h_hi, h_lo);
    }

    // attention: t1 = relu(h @ Wa1 + ba1)
    mma_gemm<256, true, false, true><<<dim3(1, MT), 256, SMEM>>>(
        h_hi, h_lo, wa1_hi, wa1_lo, ba1, t1, nullptr, nullptr, N_NODES, HID / 2);
    {
        long tot = (long)N_NODES * 32;
        attn_a_kernel<<<(unsigned)((tot + 255) / 256), 256>>>(t1, Wa2, ba2, a_out);
    }

    pool_kernel<<<N_GRAPHS, HID>>>(h, a_out, batch, pool);
    classifier_kernel<<<N_GRAPHS, 256>>>(pool, Wc1, bc1, Wc2, bc2, Wc3, bc3, preds);
}

// round 14
// speedup vs baseline: 1.4386x; 1.0606x over previous
#include <cuda_runtime.h>
#include <cuda_bf16.h>
#include <cstdint>
#include <math.h>

#define N_NODES 50000
#define MPAD    50048   // multiple of 128; pad rows stay zero (.bss)
#define N_EDGES 800000
#define N_GRAPHS 128
#define IN_DIM  100
#define HID     256
#define STEPS   5

// ---------------- scratch (device globals; zero-initialized, no allocation) ----
__device__ float d_h [MPAD * HID];                  // h fp32 (gather/pool/GRU-old)
__device__ float d_g [(size_t)N_NODES * 1024];      // gate pre-acts [r|z|i_n|h_n]
__device__ float d_t1[(size_t)N_NODES * (HID / 2)];
__device__ float d_pool[N_GRAPHS * 2 * HID];

// concat activation buffer: cols [0,256)=agg, [256,512)=h   (bf16 hi/lo)
__device__ __nv_bfloat16 d_cat_hi[(size_t)MPAD * 512], d_cat_lo[(size_t)MPAD * 512];
__device__ __nv_bfloat16 d_hs_hi[MPAD * HID], d_hs_lo[MPAD * HID];
__device__ __nv_bfloat16 d_x_hi [MPAD * 128], d_x_lo [MPAD * 128];

// Wcat [1024 rows, 512 K]: rows 0-255 r (Wih|Whh), 256-511 z (Wih|Whh),
// 512-767 i_n (Wih|0), 768-1023 h_n (0|Whh)
__device__ __nv_bfloat16 d_wcat_hi[1024 * 512], d_wcat_lo[1024 * 512];
__device__ __nv_bfloat16 d_wt_hi [STEPS * 256 * 256], d_wt_lo [STEPS * 256 * 256];
__device__ __nv_bfloat16 d_wa1_hi[128 * 256], d_wa1_lo[128 * 256];
__device__ __nv_bfloat16 d_win_hi[256 * 128], d_win_lo[256 * 128];

// ---------------- CSR-by-destination (built once per call) ----------------
__device__ int d_deg [N_NODES];
__device__ int d_fill[N_NODES];
__device__ int d_offs[N_NODES + 1];
__device__ int d_eidx[N_EDGES];     // src node ids bucketed by dst

// ================= PTX helpers (sm_80-baseline only) =================
__device__ __forceinline__ uint32_t smem_u32(const void* p) {
    uint32_t a;
    asm("{ .reg .u64 t; cvta.to.shared.u64 t, %1; cvt.u32.u64 %0, t; }" : "=r"(a) : "l"(p));
    return a;
}
__device__ __forceinline__ void cp16(uint32_t s, const void* g) {
    asm volatile("cp.async.cg.shared.global [%0], [%1], 16;" :: "r"(s), "l"(g));
}
#define CP_COMMIT() asm volatile("cp.async.commit_group;" ::: "memory")
#define CP_WAIT(N)  asm volatile("cp.async.wait_group %0;" :: "n"(N) : "memory")

__device__ __forceinline__ void ldm4(uint32_t& r0, uint32_t& r1, uint32_t& r2, uint32_t& r3,
                                     uint32_t a) {
    asm volatile("ldmatrix.sync.aligned.m8n8.x4.shared.b16 {%0,%1,%2,%3}, [%4];"
                 : "=r"(r0), "=r"(r1), "=r"(r2), "=r"(r3) : "r"(a));
}
__device__ __forceinline__ void mma_bf16(float* c, const uint32_t* a, const uint32_t* b) {
    asm volatile(
        "mma.sync.aligned.m16n8k16.row.col.f32.bf16.bf16.f32 "
        "{%0,%1,%2,%3}, {%4,%5,%6,%7}, {%8,%9}, {%0,%1,%2,%3};"
        : "+f"(c[0]), "+f"(c[1]), "+f"(c[2]), "+f"(c[3])
        : "r"(a[0]), "r"(a[1]), "r"(a[2]), "r"(a[3]), "r"(b[0]), "r"(b[1]));
}
__device__ __forceinline__ uint32_t pack_hi2(__nv_bfloat16 a, __nv_bfloat16 b) {
    return ((uint32_t)__bfloat16_as_ushort(b) << 16) | (uint32_t)__bfloat16_as_ushort(a);
}
__device__ __forceinline__ uint32_t pack_bf2(float a, float b) {
    return pack_hi2(__float2bfloat16(a), __float2bfloat16(b));
}

// ================= mma.sync GEMM: C[M, N] = A[M, K] @ B[N, K]^T ================
// A bf16 hi/lo, element row stride ASTRIDE. B bf16 hi/lo K-contig, row stride KTOT.
// Split product: AhBh + AhBl + AlBh, fp32 accumulation.
// CTA 128x128, 8 warps (4x2), warp tile 32x64, K chunk 32, double-buffered.
// GATEK: per-column-tile K range (tiles 0-3 full, 4-5 first half, 6-7 second half).
template <int KTOT, int ASTRIDE, bool GATEK, bool WF32, bool WBF16, bool RELU>
__global__ __launch_bounds__(256) void mma_gemm(
    const __nv_bfloat16* __restrict__ Ah, const __nv_bfloat16* __restrict__ Al,
    const __nv_bfloat16* __restrict__ Bh, const __nv_bfloat16* __restrict__ Bl,
    const float* __restrict__ bias,
    float* __restrict__ Cf, __nv_bfloat16* __restrict__ Cbh, __nv_bfloat16* __restrict__ Cbl,
    int M, int CFS, int CBS)
{
    constexpr int CH = KTOT / 32;
    constexpr int RSTRIDE = 80;          // 64B data + 16B pad per 32-elem bf16 row
    constexpr int MAT = 128 * RSTRIDE;   // 10240 B per matrix per stage
    extern __shared__ char smem[];
    const uint32_t sb = smem_u32(smem);

    const int tid = threadIdx.x;
    const int wid = tid >> 5, lane = tid & 31;
    const int warp_m = wid & 3, warp_n = wid >> 2;
    const int row0 = blockIdx.y * 128;
    const int ncol0 = blockIdx.x * 128;

    int c_begin = 0, c_end = CH;
    if constexpr (GATEK) {
        if (blockIdx.x >= 6) c_begin = CH / 2;       // h_n rows: K[256:512)
        else if (blockIdx.x >= 4) c_end = CH / 2;    // i_n rows: K[0:256)
    }

    float acc[2][8][4];
#pragma unroll
    for (int tm = 0; tm < 2; tm++)
#pragma unroll
        for (int nt = 0; nt < 8; nt++)
#pragma unroll
            for (int c = 0; c < 4; c++) acc[tm][nt][c] = 0.f;

    auto load_stage = [&](int c, int st) {
        const int k0 = c * 32;
        const uint32_t base = sb + st * (4 * MAT);
#pragma unroll
        for (int i = 0; i < 2; i++) {
            int l = tid + i * 256;       // 512 uint4 per matrix
            int row = l >> 2, q = l & 3;
            uint32_t so = (uint32_t)(row * RSTRIDE + q * 16);
            size_t ea = (size_t)(row0 + row) * ASTRIDE + k0 + q * 8;
            size_t eb = (size_t)(ncol0 + row) * KTOT + k0 + q * 8;
            cp16(base + so,           Ah + ea);
            cp16(base + MAT + so,     Al + ea);
            cp16(base + 2 * MAT + so, Bh + eb);
            cp16(base + 3 * MAT + so, Bl + eb);
        }
    };

    load_stage(c_begin, c_begin & 1);
    CP_COMMIT();

    const int ar = (lane & 7) + ((lane >> 3) & 1) * 8;
    const int akh = lane >> 4;
    const int bn = (lane >> 4);
    const int bk = (lane >> 3) & 1;

    for (int c = c_begin; c < c_end; c++) {
        const int st = c & 1;
        if (c + 1 < c_end) {
            load_stage(c + 1, st ^ 1);
            CP_COMMIT();
            CP_WAIT(1);
        } else {
            CP_WAIT(0);
        }
        __syncthreads();

        const uint32_t base = sb + st * (4 * MAT);
#pragma unroll
        for (int j = 0; j < 2; j++) {    // two k16 per chunk
            uint32_t ah[2][4], al[2][4];
#pragma unroll
            for (int tm = 0; tm < 2; tm++) {
                uint32_t ao = base + (uint32_t)((warp_m * 32 + tm * 16 + ar) * RSTRIDE +
                                                j * 32 + akh * 16);
                ldm4(ah[tm][0], ah[tm][1], ah[tm][2], ah[tm][3], ao);
                ldm4(al[tm][0], al[tm][1], al[tm][2], al[tm][3], ao + MAT);
            }
            uint32_t bh[4][4], bl[4][4];
#pragma unroll
            for (int q = 0; q < 4; q++) {
                int nrow = warp_n * 64 + (2 * q + bn) * 8 + (lane & 7);
                uint32_t bo = base + 2 * MAT +
                              (uint32_t)(nrow * RSTRIDE + j * 32 + bk * 16);
                ldm4(bh[q][0], bh[q][1], bh[q][2], bh[q][3], bo);
                ldm4(bl[q][0], bl[q][1], bl[q][2], bl[q][3], bo + MAT);
            }
#pragma unroll
            for (int tm = 0; tm < 2; tm++)
#pragma unroll
                for (int nt = 0; nt < 8; nt++) {
                    int q = nt >> 1, o = (nt & 1) * 2;
                    mma_bf16(acc[tm][nt], ah[tm], &bh[q][o]);
                    mma_bf16(acc[tm][nt], ah[tm], &bl[q][o]);
                    mma_bf16(acc[tm][nt], al[tm], &bh[q][o]);
                }
        }
        __syncthreads();
    }

    // ---- epilogue ----
#pragma unroll
    for (int tm = 0; tm < 2; tm++) {
        int rbase = row0 + warp_m * 32 + tm * 16 + (lane >> 2);
#pragma unroll
        for (int half = 0; half < 2; half++) {
            int row_g = rbase + half * 8;
            if (row_g >= M) continue;
#pragma unroll
            for (int nt = 0; nt < 8; nt++) {
                int col = ncol0 + warp_n * 64 + nt * 8 + (lane & 3) * 2;
                float v0 = acc[tm][nt][half * 2 + 0];
                float v1 = acc[tm][nt][half * 2 + 1];
                if (bias) { v0 += bias[col]; v1 += bias[col + 1]; }
                if (RELU) { v0 = fmaxf(v0, 0.f); v1 = fmaxf(v1, 0.f); }
                if (WF32)
                    *(float2*)(Cf + (size_t)row_g * CFS + col) = make_float2(v0, v1);
                if (WBF16) {
                    __nv_bfloat16 h0 = __float2bfloat16(v0);
                    __nv_bfloat16 h1 = __float2bfloat16(v1);
                    float l0 = v0 - __bfloat162float(h0);
                    float l1 = v1 - __bfloat162float(h1);
                    *(uint32_t*)(Cbh + (size_t)row_g * CBS + col) = pack_hi2(h0, h1);
                    *(uint32_t*)(Cbl + (size_t)row_g * CBS + col) = pack_bf2(l0, l1);
                }
            }
        }
    }
}

// ================= CSR build (once per call) =================
__global__ void zero_csr_kernel(int* deg, int* fill) {
    int i = blockIdx.x * blockDim.x + threadIdx.x;
    if (i < N_NODES) { deg[i] = 0; fill[i] = 0; }
}
__global__ void hist_kernel(const int* __restrict__ dst, int* __restrict__ deg) {
    int e = blockIdx.x * blockDim.x + threadIdx.x;
    if (e < N_EDGES) atomicAdd(&deg[dst[e]], 1);
}
__global__ __launch_bounds__(1024) void scan_kernel(const int* __restrict__ deg,
                                                    int* __restrict__ offs) {
    __shared__ int part[1024];
    const int tid = threadIdx.x;
    const int per = (N_NODES + 1023) / 1024;  // 49
    int s0 = tid * per;
    int s1 = s0 + per; if (s1 > N_NODES) s1 = N_NODES;
    int sum = 0;
    for (int i = s0; i < s1; i++) sum += deg[i];
    part[tid] = sum;
    __syncthreads();
    for (int off = 1; off < 1024; off <<= 1) {
        int v = 0;
        if (tid >= off) v = part[tid - off];
        __syncthreads();
        if (tid >= off) part[tid] += v;
        __syncthreads();
    }
    int run = (tid == 0) ? 0 : part[tid - 1];
    for (int i = s0; i < s1; i++) { offs[i] = run; run += deg[i]; }
    if (tid == 1023) offs[N_NODES] = run;
}
__global__ void fill_kernel(const int* __restrict__ src, const int* __restrict__ dst,
                            const int* __restrict__ offs, int* __restrict__ fill,
                            int* __restrict__ eidx) {
    int e = blockIdx.x * blockDim.x + threadIdx.x;
    if (e >= N_EDGES) return;
    int d = dst[e];
    int pos = offs[d] + atomicAdd(&fill[d], 1);
    eidx[pos] = src[e];
}

// ====== atomic-free gather with direct bf16 split: hs[n] = sum h[src[e]] ======
__global__ __launch_bounds__(128) void gather_kernel(
    const float* __restrict__ h, const int* __restrict__ offs,
    const int* __restrict__ eidx, __nv_bfloat16* __restrict__ hh,
    __nv_bfloat16* __restrict__ hl) {
    int node = blockIdx.x;
    int t = threadIdx.x;                   // 128 threads, float2 each
    int lo = offs[node], hi = offs[node + 1];
    float2 acc = make_float2(0.f, 0.f);
    for (int j = lo; j < hi; j++) {
        int s = __ldg(eidx + j);
        float2 v = *(const float2*)(h + (size_t)s * HID + t * 2);
        acc.x += v.x; acc.y += v.y;
    }
    size_t ob = (size_t)node * HID + t * 2;
    __nv_bfloat16 q0 = __float2bfloat16(acc.x), q1 = __float2bfloat16(acc.y);
    *(uint32_t*)(hh + ob) = pack_hi2(q0, q1);
    *(uint32_t*)(hl + ob) = pack_bf2(acc.x - __bfloat162float(q0),
                                     acc.y - __bfloat162float(q1));
}

// ================= weight conversion kernels =================
__device__ __forceinline__ void split_store(float v, __nv_bfloat16* ph, __nv_bfloat16* pl) {
    __nv_bfloat16 h = __float2bfloat16(v);
    *ph = h;
    *pl = __float2bfloat16(v - __bfloat162float(h));
}

// Wcat [1024, 512] from W_ih [768,256], W_hh [768,256]
__global__ void conv_wcat(const float* __restrict__ wih, const float* __restrict__ whh,
                          __nv_bfloat16* dh, __nv_bfloat16* dl) {
    int idx = blockIdx.x * blockDim.x + threadIdx.x;
    if (idx >= 1024 * 512) return;
    int n = idx >> 9, k = idx & 511;
    float v;
    if (n < 512)        v = (k < 256) ? wih[n * 256 + k] : whh[n * 256 + (k - 256)];
    else if (n < 768)   v = (k < 256) ? wih[n * 256 + k] : 0.f;          // i_n
    else                v = (k < 256) ? 0.f : whh[(n - 256) * 256 + (k - 256)]; // h_n
    split_store(v, dh + idx, dl + idx);
}
// ggc_w[s][k][n] -> wt[s][n][k]
__global__ void conv_ggc(const float* __restrict__ src, __nv_bfloat16* dh, __nv_bfloat16* dl) {
    int idx = blockIdx.x * blockDim.x + threadIdx.x;
    if (idx >= STEPS * 256 * 256) return;
    int s = idx >> 16, rem = idx & 65535;
    int nn = rem >> 8, kk = rem & 255;
    split_store(src[(size_t)s * 65536 + kk * 256 + nn], dh + idx, dl + idx);
}
// Wa1[k(256)][n(128)] -> wa1t[n][k]
__global__ void conv_wa1(const float* __restrict__ src, __nv_bfloat16* dh, __nv_bfloat16* dl) {
    int idx = blockIdx.x * blockDim.x + threadIdx.x;
    if (idx >= 128 * 256) return;
    int nn = idx >> 8, kk = idx & 255;
    split_store(src[kk * 128 + nn], dh + idx, dl + idx);
}
// W_in[k(100)][n(256)] -> wint[n][k(128 padded)]
__global__ void conv_win(const float* __restrict__ src, __nv_bfloat16* dh, __nv_bfloat16* dl) {
    int idx = blockIdx.x * blockDim.x + threadIdx.x;
    if (idx >= 256 * 128) return;
    int nn = idx >> 7, kk = idx & 127;
    split_store((kk < IN_DIM) ? src[kk * 256 + nn] : 0.f, dh + idx, dl + idx);
}
// x[r][100] -> x_hi/lo[r][128 padded]
__global__ void conv_x(const float* __restrict__ x, __nv_bfloat16* dh, __nv_bfloat16* dl) {
    long idx = (long)blockIdx.x * blockDim.x + threadIdx.x;
    if (idx >= (long)N_NODES * 128) return;
    int r = (int)(idx >> 7), k = (int)(idx & 127);
    split_store((k < IN_DIM) ? x[(size_t)r * IN_DIM + k] : 0.f, dh + idx, dl + idx);
}

// ================= GRU elementwise: reads g[·,1024], writes h + cat split ======
__global__ void gru_kernel(const float* __restrict__ g,
                           const float* __restrict__ b_ih, const float* __restrict__ b_hh,
                           float* __restrict__ h, __nv_bfloat16* __restrict__ ch,
                           __nv_bfloat16* __restrict__ cl) {
    long idx = (long)blockIdx.x * blockDim.x + threadIdx.x;
    if (idx >= (long)N_NODES * 64) return;
    int n = (int)(idx >> 6);
    int d = (int)(idx & 63) << 2;
    size_t gb = (size_t)n * 1024 + d;
    float4 rs  = *(const float4*)(g + gb);
    float4 zs  = *(const float4*)(g + gb + 256);
    float4 inn = *(const float4*)(g + gb + 512);
    float4 hnn = *(const float4*)(g + gb + 768);
    float4 bir = *(const float4*)(b_ih + d);
    float4 biz = *(const float4*)(b_ih + 256 + d);
    float4 bin_ = *(const float4*)(b_ih + 512 + d);
    float4 bhr = *(const float4*)(b_hh + d);
    float4 bhz = *(const float4*)(b_hh + 256 + d);
    float4 bhn = *(const float4*)(b_hh + 512 + d);
    size_t hb = (size_t)n * HID + d;
    float4 hv = *(const float4*)(h + hb);
    float o[4];
#pragma unroll
    for (int c = 0; c < 4; c++) {
        float r = 1.f / (1.f + expf(-(((const float*)&rs)[c] + ((const float*)&bir)[c] +
                                      ((const float*)&bhr)[c])));
        float z = 1.f / (1.f + expf(-(((const float*)&zs)[c] + ((const float*)&biz)[c] +
                                      ((const float*)&bhz)[c])));
        float i_n = ((const float*)&inn)[c] + ((const float*)&bin_)[c];
        float h_n = ((const float*)&hnn)[c] + ((const float*)&bhn)[c];
        float nn = tanhf(i_n + r * h_n);
        o[c] = (1.f - z) * nn + z * ((const float*)&hv)[c];
    }
    *(float4*)(h + hb) = make_float4(o[0], o[1], o[2], o[3]);
    size_t cb = (size_t)n * 512 + 256 + d;
    __nv_bfloat16 q0 = __float2bfloat16(o[0]), q1 = __float2bfloat16(o[1]);
    __nv_bfloat16 q2 = __float2bfloat16(o[2]), q3 = __float2bfloat16(o[3]);
    uint2 uh, ul;
    uh.x = pack_hi2(q0, q1);
    uh.y = pack_hi2(q2, q3);
    ul.x = pack_bf2(o[0] - __bfloat162float(q0), o[1] - __bfloat162float(q1));
    ul.y = pack_bf2(o[2] - __bfloat162float(q2), o[3] - __bfloat162float(q3));
    *(uint2*)(ch + cb) = uh;
    *(uint2*)(cl + cb) = ul;
}

// h = relu(h), re-emit split into cat(+256)
__global__ void relu_h_kernel(float* __restrict__ h, __nv_bfloat16* __restrict__ ch,
                              __nv_bfloat16* __restrict__ cl) {
    long idx = (long)blockIdx.x * blockDim.x + threadIdx.x;
    if (idx >= (long)N_NODES * 64) return;
    int n = (int)(idx >> 6);
    int d = (int)(idx & 63) << 2;
    size_t hb = (size_t)n * HID + d;
    float4 v = *(const float4*)(h + hb);
    v.x = fmaxf(v.x, 0.f); v.y = fmaxf(v.y, 0.f);
    v.z = fmaxf(v.z, 0.f); v.w = fmaxf(v.w, 0.f);
    *(float4*)(h + hb) = v;
    size_t cb = (size_t)n * 512 + 256 + d;
    __nv_bfloat16 q0 = __float2bfloat16(v.x), q1 = __float2bfloat16(v.y);
    __nv_bfloat16 q2 = __float2bfloat16(v.z), q3 = __float2bfloat16(v.w);
    uint2 uh, ul;
    uh.x = pack_hi2(q0, q1);
    uh.y = pack_hi2(q2, q3);
    ul.x = pack_bf2(v.x - __bfloat162float(q0), v.y - __bfloat162float(q1));
    ul.y = pack_bf2(v.z - __bfloat162float(q2), v.w - __bfloat162float(q3));
    *(uint2*)(ch + cb) = uh;
    *(uint2*)(cl + cb) = ul;
}

// a = sigmoid(t1 @ Wa2 + ba2)
__global__ void attn_a_kernel(const float* __restrict__ t1, const float* __restrict__ Wa2,
                              const float* __restrict__ ba2, float* __restrict__ a) {
    long idx = (long)blockIdx.x * blockDim.x + threadIdx.x;
    int warp = (int)(idx >> 5);
    int lane = (int)(idx & 31);
    if (warp >= N_NODES) return;
    float s = 0.f;
#pragma unroll
    for (int k = lane; k < HID / 2; k += 32) s += t1[(size_t)warp * (HID / 2) + k] * Wa2[k];
#pragma unroll
    for (int o = 16; o > 0; o >>= 1) s += __shfl_xor_sync(0xFFFFFFFFu, s, o);
    if (lane == 0) a[warp] = 1.f / (1.f + expf(-(s + ba2[0])));
}

__global__ void pool_kernel(const float* __restrict__ h, const float* __restrict__ a,
                            const int* __restrict__ batch, float* __restrict__ pool) {
    int g = blockIdx.x;
    int d = threadIdx.x;
    __shared__ int s_lo, s_hi;
    if (d == 0) {
        int lo = 0, hi = N_NODES;
        while (lo < hi) { int mid = (lo + hi) >> 1; if (batch[mid] < g) lo = mid + 1; else hi = mid; }
        s_lo = lo;
        lo = 0; hi = N_NODES;
        while (lo < hi) { int mid = (lo + hi) >> 1; if (batch[mid] < g + 1) lo = mid + 1; else hi = mid; }
        s_hi = lo;
    }
    __syncthreads();
    int lo = s_lo, hi = s_hi;
    float sum = 0.f, mx = 0.f;  // wx >= 0 so 0-init max matches ref
    for (int i = lo; i < hi; i++) {
        float w = h[(size_t)i * HID + d] * a[i];
        sum += w;
        mx = fmaxf(mx, w);
    }
    int cnt = hi - lo;
    pool[(size_t)g * 2 * HID + d] = sum / (float)(cnt > 1 ? cnt : 1);
    pool[(size_t)g * 2 * HID + HID + d] = (cnt > 0) ? mx : 0.f;
}

__global__ void classifier_kernel(const float* __restrict__ pool,
                                  const float* __restrict__ Wc1, const float* __restrict__ bc1,
                                  const float* __restrict__ Wc2, const float* __restrict__ bc2,
                                  const float* __restrict__ Wc3, const float* __restrict__ bc3,
                                  float* __restrict__ preds) {
    int g = blockIdx.x;
    int t = threadIdx.x;
    __shared__ float sg[2 * HID];
    __shared__ float t1[HID];
    __shared__ float t2[HID / 2];
    sg[t] = pool[(size_t)g * 2 * HID + t];
    sg[t + HID] = pool[(size_t)g * 2 * HID + HID + t];
    __syncthreads();
    {
        float acc = bc1[t];
        for (int k = 0; k < 2 * HID; k++) acc += sg[k] * Wc1[(size_t)k * HID + t];
        t1[t] = fmaxf(acc, 0.f);
    }
    __syncthreads();
    if (t < HID / 2) {
        float acc = bc2[t];
        for (int k = 0; k < HID; k++) acc += t1[k] * Wc2[(size_t)k * (HID / 2) + t];
        t2[t] = fmaxf(acc, 0.f);
    }
    __syncthreads();
    if (t < 2) {
        float acc = bc3[t];
        for (int k = 0; k < HID / 2; k++) acc += t2[k] * Wc3[(size_t)k * 2 + t];
        preds[g * 2 + t] = acc;
    }
}

// ================= launch =================
extern "C" void kernel_launch(void* const* d_in, const int* in_sizes, int n_in,
                              void* d_out, int out_size) {
    const float* x     = (const float*)d_in[0];
    const int*   edge  = (const int*)d_in[1];
    const int*   batch = (const int*)d_in[2];
    const float* W_in  = (const float*)d_in[3];
    const float* b_in  = (const float*)d_in[4];
    const float* ggc_w = (const float*)d_in[5];
    const float* W_ih  = (const float*)d_in[6];
    const float* W_hh  = (const float*)d_in[7];
    const float* b_ih  = (const float*)d_in[8];
    const float* b_hh  = (const float*)d_in[9];
    const float* Wa1   = (const float*)d_in[10];
    const float* ba1   = (const float*)d_in[11];
    const float* Wa2   = (const float*)d_in[12];
    const float* ba2   = (const float*)d_in[13];
    const float* Wc1   = (const float*)d_in[14];
    const float* bc1   = (const float*)d_in[15];
    const float* Wc2   = (const float*)d_in[16];
    const float* bc2   = (const float*)d_in[17];
    const float* Wc3   = (const float*)d_in[18];
    const float* bc3   = (const float*)d_in[19];

    float* out   = (float*)d_out;
    float* preds = out;
    float* a_out = out + N_GRAPHS * 2;

    float *h, *g, *t1, *pool;
    __nv_bfloat16 *cat_hi, *cat_lo, *hs_hi, *hs_lo, *x_hi, *x_lo;
    __nv_bfloat16 *wcat_hi, *wcat_lo, *wt_hi, *wt_lo, *wa1_hi, *wa1_lo, *win_hi, *win_lo;
    int *deg, *fill, *offs, *eidx;
    cudaGetSymbolAddress((void**)&h, d_h);
    cudaGetSymbolAddress((void**)&g, d_g);
    cudaGetSymbolAddress((void**)&t1, d_t1);
    cudaGetSymbolAddress((void**)&pool, d_pool);
    cudaGetSymbolAddress((void**)&cat_hi, d_cat_hi);
    cudaGetSymbolAddress((void**)&cat_lo, d_cat_lo);
    cudaGetSymbolAddress((void**)&hs_hi, d_hs_hi);
    cudaGetSymbolAddress((void**)&hs_lo, d_hs_lo);
    cudaGetSymbolAddress((void**)&x_hi, d_x_hi);
    cudaGetSymbolAddress((void**)&x_lo, d_x_lo);
    cudaGetSymbolAddress((void**)&wcat_hi, d_wcat_hi);
    cudaGetSymbolAddress((void**)&wcat_lo, d_wcat_lo);
    cudaGetSymbolAddress((void**)&wt_hi, d_wt_hi);
    cudaGetSymbolAddress((void**)&wt_lo, d_wt_lo);
    cudaGetSymbolAddress((void**)&wa1_hi, d_wa1_hi);
    cudaGetSymbolAddress((void**)&wa1_lo, d_wa1_lo);
    cudaGetSymbolAddress((void**)&win_hi, d_win_hi);
    cudaGetSymbolAddress((void**)&win_lo, d_win_lo);
    cudaGetSymbolAddress((void**)&deg, d_deg);
    cudaGetSymbolAddress((void**)&fill, d_fill);
    cudaGetSymbolAddress((void**)&offs, d_offs);
    cudaGetSymbolAddress((void**)&eidx, d_eidx);

    const int* src = edge;
    const int* dst = edge + N_EDGES;

    const int SMEM = 2 * 4 * (128 * 80);  // 81920 B
    cudaFuncSetAttribute(mma_gemm<128, 128, false, true, true, true>,
                         cudaFuncAttributeMaxDynamicSharedMemorySize, SMEM);
    cudaFuncSetAttribute(mma_gemm<256, 256, false, false, true, false>,
                         cudaFuncAttributeMaxDynamicSharedMemorySize, SMEM);
    cudaFuncSetAttribute(mma_gemm<512, 512, true, true, false, false>,
                         cudaFuncAttributeMaxDynamicSharedMemorySize, SMEM);
    cudaFuncSetAttribute(mma_gemm<256, 512, false, true, false, true>,
                         cudaFuncAttributeMaxDynamicSharedMemorySize, SMEM);

    const int MT = (N_NODES + 127) / 128;  // 391

    // ---- CSR build (graph constant within a call) ----
    zero_csr_kernel<<<(N_NODES + 255) / 256, 256>>>(deg, fill);
    hist_kernel<<<(N_EDGES + 255) / 256, 256>>>(dst, deg);
    scan_kernel<<<1, 1024>>>(deg, offs);
    fill_kernel<<<(N_EDGES + 255) / 256, 256>>>(src, dst, offs, fill, eidx);

    // ---- weight / input conversions ----
    conv_wcat<<<(1024 * 512 + 255) / 256, 256>>>(W_ih, W_hh, wcat_hi, wcat_lo);
    conv_ggc<<<(STEPS * 65536 + 255) / 256, 256>>>(ggc_w, wt_hi, wt_lo);
    conv_wa1<<<(128 * 256 + 255) / 256, 256>>>(Wa1, wa1_hi, wa1_lo);
    conv_win<<<(256 * 128 + 255) / 256, 256>>>(W_in, win_hi, win_lo);
    {
        long tot = (long)N_NODES * 128;
        conv_x<<<(unsigned)((tot + 255) / 256), 256>>>(x, x_hi, x_lo);
    }

    // ---- input projection: h = relu(x @ W_in + b_in); split into cat[+256] ----
    mma_gemm<128, 128, false, true, true, true><<<dim3(2, MT), 256, SMEM>>>(
        x_hi, x_lo, win_hi, win_lo, b_in, h, cat_hi + 256, cat_lo + 256,
        N_NODES, HID, 512);

    for (int s = 0; s < STEPS; s++) {
        // hs[n] = sum over in-edges of h[src]  (CSR gather, direct bf16 split)
        gather_kernel<<<N_NODES, 128>>>(h, offs, eidx, hs_hi, hs_lo);
        // agg = hs @ w[s] -> cat cols [0,256)
        mma_gemm<256, 256, false, false, true, false><<<dim3(2, MT), 256, SMEM>>>(
            hs_hi, hs_lo, wt_hi + (size_t)s * 65536, wt_lo + (size_t)s * 65536,
            nullptr, nullptr, cat_hi, cat_lo, N_NODES, 0, 512);
        // g = cat @ Wcat^T  (r|z combined K=512; i_n K[0:256); h_n K[256:512))
        mma_gemm<512, 512, true, true, false, false><<<dim3(8, MT), 256, SMEM>>>(
            cat_hi, cat_lo, wcat_hi, wcat_lo,
            nullptr, g, nullptr, nullptr, N_NODES, 1024, 0);
        // GRU: h = (1-z)*tanh(i_n + r*h_n) + z*h ; re-split into cat[+256]
        {
            long tot = (long)N_NODES * 64;
            gru_kernel<<<(unsigned)((tot + 255) / 256), 256>>>(
                g, b_ih, b_hh, h, cat_hi, cat_lo);
        }
    }

    {
        long tot = (long)N_NODES * 64;
        relu_h_kernel<<<(unsigned)((tot + 255) / 256), 256>>>(h, cat_hi, cat_lo);
    }

    // attention: t1 = relu(h @ Wa1 + ba1)   (A = cat cols [256,512))
    mma_gemm<256, 512, false, true, false, true><<<dim3(1, MT), 256, SMEM>>>(
        cat_hi + 256, cat_lo + 256, wa1_hi, wa1_lo, ba1, t1, nullptr, nullptr,
        N_NODES, HID / 2, 0);
    {
        long tot = (long)N_NODES * 32;
        attn_a_kernel<<<(unsigned)((tot + 255) / 256), 256>>>(t1, Wa2, ba2, a_out);
    }

    pool_kernel<<<N_GRAPHS, HID>>>(h, a_out, batch, pool);
    classifier_kernel<<<N_GRAPHS, 256>>>(pool, Wc1, bc1, Wc2, bc2, Wc3, bc3, preds);
}